// round 4
// baseline (speedup 1.0000x reference)
#include <cuda_runtime.h>
#include <cstdint>

#define GROUPS  2048
#define NT      16     // 16 b-tiles of 64 rows
#define S       68     // smem row stride (words): bank = (4*row + col) % 32, conflict-free frags

// smem word layout
#define OFF_X0  0
#define OFF_X1  4352
#define OFF_H0  8704
#define OFF_H1  13056
#define OFF_B0  17408
#define OFF_B1  17472
#define SMEM_WORDS 17536
#define SMEM_BYTES (SMEM_WORDS * 4)

__device__ __forceinline__ uint32_t f2tf32(float f) {
    uint32_t u; asm("cvt.rna.tf32.f32 %0, %1;" : "=r"(u) : "f"(f)); return u;
}

__device__ __forceinline__ void mma_tf32(float& d0, float& d1, float& d2, float& d3,
                                         uint32_t a0, uint32_t a1, uint32_t a2, uint32_t a3,
                                         uint32_t b0, uint32_t b1) {
    asm volatile("mma.sync.aligned.m16n8k8.row.col.f32.tf32.tf32.f32 "
                 "{%0,%1,%2,%3}, {%4,%5,%6,%7}, {%8,%9}, {%0,%1,%2,%3};"
                 : "+f"(d0), "+f"(d1), "+f"(d2), "+f"(d3)
                 : "r"(a0), "r"(a1), "r"(a2), "r"(a3), "r"(b0), "r"(b1));
}

// One CTA per group, 256 threads.
// Warps 0-3: layer-0 crew (W0 frags in regs, warp tile m16 x n64).
// Warps 4-7: layer-1 crew (W1 frags in regs, warp tile m16 x n64).
// Software pipeline: L0 crew processes tile t while L1 crew processes tile t-1.
// X and h double-buffered; one __syncthreads per pipeline stage.
extern "C" __global__ void __launch_bounds__(256, 1) convnn_spec(
    const float* __restrict__ x,  const float* __restrict__ W0,
    const float* __restrict__ b0, const float* __restrict__ W1,
    const float* __restrict__ b1, float* __restrict__ out)
{
    extern __shared__ uint32_t sm[];
    float* sB0 = (float*)(sm + OFF_B0);
    float* sB1 = (float*)(sm + OFF_B1);

    const int g    = blockIdx.x;
    const int tid  = threadIdx.x;
    const int lane = tid & 31;
    const int warp = tid >> 5;
    const int gid  = lane >> 2;   // 0..7
    const int tig  = lane & 3;    // 0..3
    const int crew = warp >> 2;   // 0 = layer0, 1 = layer1
    const int mrow = (warp & 3) * 16;

    // staging indices: 256 threads x 16 words (4 float4) cover a 64x64 tile
    const int sr  = tid >> 2;          // 0..63 (row)
    const int sc  = (tid & 3) << 4;    // 0,16,32,48 (col base)

    // ---- stage weights and load this crew's fragments into registers ----
    uint32_t wf[8][8][2];   // [j-subtile s][k-chunk][b0,b1]
    #pragma unroll
    for (int layer = 0; layer < 2; layer++) {
        const float* W = (layer ? W1 : W0) + (size_t)g * 64 * 64;
        #pragma unroll
        for (int q = 0; q < 4; q++) {
            float4 w = *(const float4*)(W + (size_t)sr * 64 + sc + q * 4);
            uint32_t* d = &sm[OFF_X0 + sr * S + sc + q * 4];
            d[0] = f2tf32(w.x); d[1] = f2tf32(w.y); d[2] = f2tf32(w.z); d[3] = f2tf32(w.w);
        }
        __syncthreads();
        if (crew == layer) {
            #pragma unroll
            for (int s = 0; s < 8; s++) {
                const int jr = OFF_X0 + (s * 8 + gid) * S;
                #pragma unroll
                for (int kc = 0; kc < 8; kc++) {
                    wf[s][kc][0] = sm[jr + kc * 8 + tig];
                    wf[s][kc][1] = sm[jr + kc * 8 + tig + 4];
                }
            }
        }
        __syncthreads();
    }
    if (tid < 64)       sB0[tid]      = b0[(size_t)g * 64 + tid];
    else if (tid < 128) sB1[tid - 64] = b1[(size_t)g * 64 + (tid - 64)];

    // ---- stage tile 0 into X[0]; prefetch tile 1 into registers ----
    #pragma unroll
    for (int q = 0; q < 4; q++) {
        float4 v = *(const float4*)(x + (size_t)sr * 64 + sc + q * 4);
        uint32_t* d = &sm[OFF_X0 + sr * S + sc + q * 4];
        d[0] = f2tf32(v.x); d[1] = f2tf32(v.y); d[2] = f2tf32(v.z); d[3] = f2tf32(v.w);
    }
    float4 px[4];
    #pragma unroll
    for (int q = 0; q < 4; q++)
        px[q] = *(const float4*)(x + (size_t)(64 + sr) * 64 + sc + q * 4);
    __syncthreads();

    for (int t = 0; t <= NT; t++) {
        // stage tile t+1 from prefetch regs into X[(t+1)&1]
        if (t + 1 < NT) {
            const int xb = OFF_X0 + ((t + 1) & 1) * (OFF_X1 - OFF_X0);
            #pragma unroll
            for (int q = 0; q < 4; q++) {
                uint32_t* d = &sm[xb + sr * S + sc + q * 4];
                d[0] = f2tf32(px[q].x); d[1] = f2tf32(px[q].y);
                d[2] = f2tf32(px[q].z); d[3] = f2tf32(px[q].w);
            }
        }
        // prefetch tile t+2
        if (t + 2 < NT) {
            #pragma unroll
            for (int q = 0; q < 4; q++)
                px[q] = *(const float4*)(x + (size_t)((t + 2) * 64 + sr) * 64 + sc + q * 4);
        }

        if (crew == 0) {
            if (t < NT) {
                // ===== layer 0 on tile t: h = leaky(X * W0^T + b0) =====
                const uint32_t* Xb = &sm[OFF_X0 + (t & 1) * (OFF_X1 - OFF_X0)];
                float acc[8][4];
                #pragma unroll
                for (int s = 0; s < 8; s++)
                    #pragma unroll
                    for (int i = 0; i < 4; i++) acc[s][i] = 0.f;
                #pragma unroll
                for (int kc = 0; kc < 8; kc++) {
                    const int k0 = kc * 8;
                    const uint32_t a0 = Xb[(mrow + gid)     * S + k0 + tig];
                    const uint32_t a1 = Xb[(mrow + gid + 8) * S + k0 + tig];
                    const uint32_t a2 = Xb[(mrow + gid)     * S + k0 + tig + 4];
                    const uint32_t a3 = Xb[(mrow + gid + 8) * S + k0 + tig + 4];
                    #pragma unroll
                    for (int s = 0; s < 8; s++)
                        mma_tf32(acc[s][0], acc[s][1], acc[s][2], acc[s][3],
                                 a0, a1, a2, a3, wf[s][kc][0], wf[s][kc][1]);
                }
                uint32_t* Hb = &sm[OFF_H0 + (t & 1) * (OFF_H1 - OFF_H0)];
                #pragma unroll
                for (int s = 0; s < 8; s++) {
                    const int j = s * 8 + 2 * tig;
                    const float bj0 = sB0[j], bj1 = sB0[j + 1];
                    float h00 = acc[s][0] + bj0; h00 = (h00 > 0.f) ? h00 : 0.2f * h00;
                    float h01 = acc[s][1] + bj1; h01 = (h01 > 0.f) ? h01 : 0.2f * h01;
                    float h10 = acc[s][2] + bj0; h10 = (h10 > 0.f) ? h10 : 0.2f * h10;
                    float h11 = acc[s][3] + bj1; h11 = (h11 > 0.f) ? h11 : 0.2f * h11;
                    *(uint2*)&Hb[(mrow + gid)     * S + j] = make_uint2(f2tf32(h00), f2tf32(h01));
                    *(uint2*)&Hb[(mrow + gid + 8) * S + j] = make_uint2(f2tf32(h10), f2tf32(h11));
                }
            }
        } else {
            if (t >= 1) {
                // ===== layer 1 on tile t-1: out = h * W1^T + b1 =====
                const uint32_t* Hb = &sm[OFF_H0 + ((t - 1) & 1) * (OFF_H1 - OFF_H0)];
                float acc[8][4];
                #pragma unroll
                for (int s = 0; s < 8; s++)
                    #pragma unroll
                    for (int i = 0; i < 4; i++) acc[s][i] = 0.f;
                #pragma unroll
                for (int kc = 0; kc < 8; kc++) {
                    const int k0 = kc * 8;
                    const uint32_t a0 = Hb[(mrow + gid)     * S + k0 + tig];
                    const uint32_t a1 = Hb[(mrow + gid + 8) * S + k0 + tig];
                    const uint32_t a2 = Hb[(mrow + gid)     * S + k0 + tig + 4];
                    const uint32_t a3 = Hb[(mrow + gid + 8) * S + k0 + tig + 4];
                    #pragma unroll
                    for (int s = 0; s < 8; s++)
                        mma_tf32(acc[s][0], acc[s][1], acc[s][2], acc[s][3],
                                 a0, a1, a2, a3, wf[s][kc][0], wf[s][kc][1]);
                }
                const int brow = (t - 1) * 64 + mrow + gid;
                #pragma unroll
                for (int s = 0; s < 8; s++) {
                    const int j = s * 8 + 2 * tig;
                    const float bj0 = sB1[j], bj1 = sB1[j + 1];
                    float2 v0 = make_float2(acc[s][0] + bj0, acc[s][1] + bj1);
                    float2 v1 = make_float2(acc[s][2] + bj0, acc[s][3] + bj1);
                    *(float2*)(out + ((size_t)brow       * GROUPS + g) * 64 + j) = v0;
                    *(float2*)(out + ((size_t)(brow + 8) * GROUPS + g) * 64 + j) = v1;
                }
            }
        }
        __syncthreads();
    }
}

extern "C" void kernel_launch(void* const* d_in, const int* in_sizes, int n_in,
                              void* d_out, int out_size) {
    const float* x  = (const float*)d_in[0];
    const float* W0 = (const float*)d_in[1];
    const float* b0 = (const float*)d_in[2];
    const float* W1 = (const float*)d_in[3];
    const float* b1 = (const float*)d_in[4];
    float* out = (float*)d_out;

    cudaFuncSetAttribute(convnn_spec, cudaFuncAttributeMaxDynamicSharedMemorySize, SMEM_BYTES);
    convnn_spec<<<GROUPS, 256, SMEM_BYTES>>>(x, W0, b0, W1, b1, out);
}